// round 13
// baseline (speedup 1.0000x reference)
#include <cuda_runtime.h>
#include <cuda_bf16.h>
#include <math.h>
#include <stdint.h>

#define N 8192
#define FIN 256
#define FOUT 64
#define NSPLIT 4    // j-splits per i-tile
#define NTILE 128   // i-rows per CTA
#define NST 64      // 32-j steps per CTA (2048 j per split)
#define BPIPE 3     // B-fragment smem ring depth

// ---------------- device scratch ----------------
__device__ float    g_Wh[(size_t)N * FOUT];
__device__ uint4    g_Bfrag[512 * 2 * 4 * 32];  // tf32 B fragments, 2 MB
__device__ unsigned g_mask[(size_t)N * 256];    // 8 MB bit-packed adj
__device__ float    g_E1[N];
__device__ float    g_E2[N];
__device__ float    g_fsrc[N];
__device__ unsigned g_gmax_enc;
__device__ float    g_Dpart[NSPLIT][(size_t)N * FOUT];
__device__ float    g_lpart[NSPLIT][N];

// ---------------- helpers ----------------
#define CP_ASYNC16(saddr, gptr) \
    asm volatile("cp.async.cg.shared.global [%0], [%1], 16;" ::"r"(saddr), "l"(gptr))
#define CP_COMMIT() asm volatile("cp.async.commit_group;")
#define CP_WAIT(n)  asm volatile("cp.async.wait_group %0;" ::"n"(n))
#define MUL_F32X2(d, a, b) \
    asm("mul.rn.f32x2 %0, %1, %2;" : "=l"(d) : "l"(a), "l"(b))
#define BAR_SYNC(id, cnt) \
    asm volatile("bar.sync %0, %1;" ::"r"(id), "r"(cnt) : "memory")

__device__ __forceinline__ uint32_t f2tf32(float x) {
    uint32_t r;
    asm("cvt.rna.tf32.f32 %0, %1;" : "=r"(r) : "f"(x));
    return r;
}
__device__ __forceinline__ void mma_tf32(float* d, uint32_t a0, uint32_t a1,
                                         uint32_t a2, uint32_t a3, uint32_t b0,
                                         uint32_t b1) {
    asm volatile(
        "mma.sync.aligned.m16n8k8.row.col.f32.tf32.tf32.f32 "
        "{%0,%1,%2,%3}, {%4,%5,%6,%7}, {%8,%9}, {%0,%1,%2,%3};"
        : "+f"(d[0]), "+f"(d[1]), "+f"(d[2]), "+f"(d[3])
        : "r"(a0), "r"(a1), "r"(a2), "r"(a3), "r"(b0), "r"(b1));
}
__device__ __forceinline__ unsigned enc_f(float x) {
    unsigned b = __float_as_uint(x);
    return (b & 0x80000000u) ? ~b : (b | 0x80000000u);
}
__device__ __forceinline__ float dec_f(unsigned k) {
    return __uint_as_float((k & 0x80000000u) ? (k & 0x7fffffffu) : ~k);
}

// ---------------------------------------------------------------------------
// Kernel A+M fused (block-specialized): blocks [0,512) Wh = h@W;
// blocks [512,4608) bit-pack adj (64 ints / thread, 16 LDG.128 MLP).
//   g_mask[r*256 + s] bit c  <=>  adj[r][s*32 + c] != 0
// ---------------------------------------------------------------------------
__global__ __launch_bounds__(256) void wh_mask_kernel(
    const float* __restrict__ h, const float* __restrict__ W,
    const int* __restrict__ adj) {
    __shared__ float Ws[128][FOUT];

    if (blockIdx.x >= 512) {  // ---- mask path ----
        const size_t w0 = ((size_t)(blockIdx.x - 512) * 256 + threadIdx.x) * 2;
        const uint4* src = (const uint4*)adj + w0 * 8;
        uint4 v[16];
#pragma unroll
        for (int q = 0; q < 16; q++) v[q] = src[q];
        unsigned m0 = 0, m1 = 0;
#pragma unroll
        for (int q = 0; q < 8; q++) {
            m0 |= (v[q].x != 0 ? 1u : 0u) << (4 * q + 0);
            m0 |= (v[q].y != 0 ? 1u : 0u) << (4 * q + 1);
            m0 |= (v[q].z != 0 ? 1u : 0u) << (4 * q + 2);
            m0 |= (v[q].w != 0 ? 1u : 0u) << (4 * q + 3);
            m1 |= (v[q + 8].x != 0 ? 1u : 0u) << (4 * q + 0);
            m1 |= (v[q + 8].y != 0 ? 1u : 0u) << (4 * q + 1);
            m1 |= (v[q + 8].z != 0 ? 1u : 0u) << (4 * q + 2);
            m1 |= (v[q + 8].w != 0 ? 1u : 0u) << (4 * q + 3);
        }
        *(uint2*)&g_mask[w0] = make_uint2(m0, m1);
        return;
    }

    // ---- Wh path ----
    if (blockIdx.x == 0 && threadIdx.x == 0) g_gmax_enc = 0u;
    const int f = threadIdx.x & 63;
    const int g = threadIdx.x >> 6;
    const int row0 = blockIdx.x * 16 + g * 4;
    float acc0 = 0.f, acc1 = 0.f, acc2 = 0.f, acc3 = 0.f;
    for (int t = 0; t < 2; t++) {
        __syncthreads();
        for (int idx = threadIdx.x; idx < 128 * FOUT; idx += 256)
            (&Ws[0][0])[idx] = W[t * 128 * FOUT + idx];
        __syncthreads();
        const float4* h0 = (const float4*)(h + (size_t)(row0 + 0) * FIN + t * 128);
        const float4* h1 = (const float4*)(h + (size_t)(row0 + 1) * FIN + t * 128);
        const float4* h2 = (const float4*)(h + (size_t)(row0 + 2) * FIN + t * 128);
        const float4* h3 = (const float4*)(h + (size_t)(row0 + 3) * FIN + t * 128);
#pragma unroll 8
        for (int k4 = 0; k4 < 32; k4++) {
            const float4 v0 = h0[k4], v1 = h1[k4], v2 = h2[k4], v3 = h3[k4];
            const float w0 = Ws[k4 * 4 + 0][f];
            const float w1 = Ws[k4 * 4 + 1][f];
            const float w2 = Ws[k4 * 4 + 2][f];
            const float w3 = Ws[k4 * 4 + 3][f];
            acc0 += v0.x * w0 + v0.y * w1 + v0.z * w2 + v0.w * w3;
            acc1 += v1.x * w0 + v1.y * w1 + v1.z * w2 + v1.w * w3;
            acc2 += v2.x * w0 + v2.y * w1 + v2.z * w2 + v2.w * w3;
            acc3 += v3.x * w0 + v3.y * w1 + v3.z * w2 + v3.w * w3;
        }
    }
    g_Wh[(size_t)(row0 + 0) * FOUT + f] = acc0;
    g_Wh[(size_t)(row0 + 1) * FOUT + f] = acc1;
    g_Wh[(size_t)(row0 + 2) * FOUT + f] = acc2;
    g_Wh[(size_t)(row0 + 3) * FOUT + f] = acc3;
}

// ---------------------------------------------------------------------------
// Kernel B: f_src, E1=exp(f_dst), E2=exp(0.2 f_dst), fused global max(f_dst).
// ---------------------------------------------------------------------------
__global__ __launch_bounds__(256) void fvec_kernel(const float* __restrict__ a) {
    __shared__ unsigned smax[8];
    const int i = blockIdx.x * blockDim.x + threadIdx.x;
    const float4* w4 = (const float4*)(g_Wh + (size_t)i * FOUT);
    const float4* a4 = (const float4*)a;
    float s = 0.f, d = 0.f;
#pragma unroll
    for (int q = 0; q < 16; q++) {
        float4 v = w4[q], as_ = a4[q], ad = a4[16 + q];
        s += v.x * as_.x + v.y * as_.y + v.z * as_.z + v.w * as_.w;
        d += v.x * ad.x + v.y * ad.y + v.z * ad.z + v.w * ad.w;
    }
    g_fsrc[i] = s;
    g_E1[i] = __expf(d);
    g_E2[i] = __expf(0.2f * d);
    unsigned k = enc_f(d);
#pragma unroll
    for (int off = 16; off > 0; off >>= 1)
        k = max(k, __shfl_xor_sync(0xffffffffu, k, off));
    if ((threadIdx.x & 31) == 0) smax[threadIdx.x >> 5] = k;
    __syncthreads();
    if (threadIdx.x == 0) {
        unsigned m = smax[0];
#pragma unroll
        for (int w = 1; w < 8; w++) m = max(m, smax[w]);
        atomicMax(&g_gmax_enc, m);
    }
}

// ---------------------------------------------------------------------------
// Kernel B2: build tf32 B fragments of Wh for mma.m16n8k8.
// ---------------------------------------------------------------------------
__global__ __launch_bounds__(256) void bfrag_kernel() {
    const int wid = blockIdx.x * 8 + (threadIdx.x >> 5);  // 0..4095
    const int lane = threadIdx.x & 31;
    const int jblock = wid >> 3, kh = (wid >> 2) & 1, ntp = wid & 3;
    const int j0 = jblock * 16 + kh * 8;
    const int f0 = ntp * 16;
    const int g = lane >> 2, tc = lane & 3;
    uint4 b;
    b.x = f2tf32(g_Wh[(size_t)(j0 + tc) * FOUT + f0 + g]);
    b.y = f2tf32(g_Wh[(size_t)(j0 + tc + 4) * FOUT + f0 + g]);
    b.z = f2tf32(g_Wh[(size_t)(j0 + tc) * FOUT + f0 + 8 + g]);
    b.w = f2tf32(g_Wh[(size_t)(j0 + tc + 4) * FOUT + f0 + 8 + g]);
    g_Bfrag[(size_t)wid * 32 + lane] = b;
}

// ---------------------------------------------------------------------------
// Kernel C (main): single-wave tensor-core attention product.
// 256 CTAs x 512 thr, 2 CTAs/SM. Warp (rg, fh): rows rg*16.., n-half fh.
// B fragments: cp.async PIPE=3 smem ring per fh-group (named barrier 2+fh,
// 256 threads; every thread commits exactly one group per step -> exact
// wait_group counts). Masks: direct L2 loads, one-step register prefetch.
// p-gen: packed f32x2 mul + FMNMX. Raw fp32 bits into mma.tf32.
// ---------------------------------------------------------------------------
__global__ __launch_bounds__(512, 2) void gat_mma_kernel() {
    __shared__ uint4  s_B[BPIPE][2][256];  // 24 KB ring
    __shared__ float2 s_E[2048];           // 16 KB
    __shared__ float  sA1[NTILE], sA2[NTILE];

    const int tid = threadIdx.x, lane = tid & 31, warp = tid >> 5;
    const int g = lane >> 2, tc = lane & 3;
    const int rg = warp >> 1, fh = warp & 1;
    const int gtid = rg * 32 + lane;  // id within fh-group (0..255)
    const int it = blockIdx.x >> 2, js = blockIdx.x & 3;
    const int row0 = it * NTILE, jbase = js * 2048;

    // constant part of this thread's B-fragment gmem offset (uint4 units):
    // src = (js*128 + 2t)*256 + kk*128 + fh*64 + sub*32 + lane
    const unsigned srcoff =
        (unsigned)((gtid >> 6) * 128 + fh * 64 + ((gtid >> 5) & 1) * 32 +
                   (gtid & 31));
    const uint32_t sbq = (uint32_t)__cvta_generic_to_shared(
        &s_B[0][fh][gtid]);  // slot 0 dst; slot stride = 2*256*16 B

    // prologue: stage B tiles 0 and 1
#pragma unroll
    for (int t = 0; t < BPIPE - 1; t++) {
        const size_t src = (size_t)(js * 128 + 2 * t) * 256 + srcoff;
        CP_ASYNC16(sbq + (uint32_t)t * (2 * 256 * 16), &g_Bfrag[src]);
        CP_COMMIT();
    }

    // stage E and per-row A1/A2
    for (int k = tid; k < 2048; k += 512)
        s_E[k] = make_float2(g_E1[jbase + k], g_E2[jbase + k]);
    if (tid < NTILE) {
        const float fs = g_fsrc[row0 + tid];
        float M = fs + dec_f(g_gmax_enc);
        M = M > 0.f ? M : 0.2f * M;  // lrelu monotone -> valid row upper bound
        sA1[tid] = __expf(fs - M);
        sA2[tid] = __expf(0.2f * fs - M);
    }
    __syncthreads();

    const int lr0 = rg * 16 + g, lr1 = lr0 + 8;
    const int gr0 = row0 + lr0, gr1 = row0 + lr1;
    float2 A0f = make_float2(sA1[lr0], sA2[lr0]);
    float2 A1f = make_float2(sA1[lr1], sA2[lr1]);
    const unsigned long long Ap0 = *(unsigned long long*)&A0f;
    const unsigned long long Ap1 = *(unsigned long long*)&A1f;

    const unsigned* mp0 = g_mask + (size_t)gr0 * 256 + js * 64;
    const unsigned* mp1 = g_mask + (size_t)gr1 * 256 + js * 64;

    float d[16];
#pragma unroll
    for (int q = 0; q < 16; q++) d[q] = 0.f;
    float l0 = 0.f, l1 = 0.f;

    unsigned m0c = mp0[0], m1c = mp1[0];

    for (int s = 0; s < NST; s++) {
        CP_WAIT(1);             // B tile s complete (tile s+1 may be pending)
        BAR_SYNC(2 + fh, 256);  // whole fh-group's tile-s writes visible

        // stage tile s+2 into ring slot (s+2)%3 (consumed at step s-1);
        // ALWAYS commit so wait counts stay exact.
        if (s + 2 < NST) {
            const int t = s + 2;
            const size_t src = (size_t)(js * 128 + 2 * t) * 256 + srcoff;
            CP_ASYNC16(sbq + (uint32_t)(t % BPIPE) * (2 * 256 * 16),
                       &g_Bfrag[src]);
        }
        CP_COMMIT();

        // prefetch next step's masks (L2)
        unsigned m0n, m1n;
        if (s < NST - 1) {
            m0n = mp0[s + 1];
            m1n = mp1[s + 1];
        }

        const uint4* Bs = &s_B[s % BPIPE][fh][0];
        const int eb = s * 32 + tc;
#pragma unroll
        for (int kk = 0; kk < 4; kk++) {
            const unsigned long long e0 =
                *(const unsigned long long*)&s_E[eb + kk * 8];
            const unsigned long long e1 =
                *(const unsigned long long*)&s_E[eb + kk * 8 + 4];
            unsigned long long t00, t10, t01, t11;
            MUL_F32X2(t00, Ap0, e0);
            MUL_F32X2(t10, Ap1, e0);
            MUL_F32X2(t01, Ap0, e1);
            MUL_F32X2(t11, Ap1, e1);
            float p00 = fmaxf(__uint_as_float((unsigned)t00),
                              __uint_as_float((unsigned)(t00 >> 32)));
            float p10 = fmaxf(__uint_as_float((unsigned)t10),
                              __uint_as_float((unsigned)(t10 >> 32)));
            float p01 = fmaxf(__uint_as_float((unsigned)t01),
                              __uint_as_float((unsigned)(t01 >> 32)));
            float p11 = fmaxf(__uint_as_float((unsigned)t11),
                              __uint_as_float((unsigned)(t11 >> 32)));
            p00 = ((m0c >> (kk * 8 + tc)) & 1u) ? p00 : 0.f;
            p10 = ((m1c >> (kk * 8 + tc)) & 1u) ? p10 : 0.f;
            p01 = ((m0c >> (kk * 8 + tc + 4)) & 1u) ? p01 : 0.f;
            p11 = ((m1c >> (kk * 8 + tc + 4)) & 1u) ? p11 : 0.f;
            l0 += p00 + p01;
            l1 += p10 + p11;
            const uint4 B0 = Bs[kk * 64 + lane];
            const uint4 B1 = Bs[kk * 64 + 32 + lane];
            const uint32_t a0 = __float_as_uint(p00);
            const uint32_t a1 = __float_as_uint(p10);
            const uint32_t a2 = __float_as_uint(p01);
            const uint32_t a3 = __float_as_uint(p11);
            mma_tf32(d + 0, a0, a1, a2, a3, B0.x, B0.y);
            mma_tf32(d + 4, a0, a1, a2, a3, B0.z, B0.w);
            mma_tf32(d + 8, a0, a1, a2, a3, B1.x, B1.y);
            mma_tf32(d + 12, a0, a1, a2, a3, B1.z, B1.w);
        }
        m0c = m0n;
        m1c = m1n;
    }

    // write D partials: tile u covers f0 = (fh*2+u)*16, halves v: +8
#pragma unroll
    for (int u = 0; u < 2; u++)
#pragma unroll
        for (int v = 0; v < 2; v++) {
            const int f = (fh * 2 + u) * 16 + v * 8 + 2 * tc;
            const float* dq = d + (u * 2 + v) * 4;
            *(float2*)&g_Dpart[js][(size_t)gr0 * FOUT + f] =
                make_float2(dq[0], dq[1]);
            *(float2*)&g_Dpart[js][(size_t)gr1 * FOUT + f] =
                make_float2(dq[2], dq[3]);
        }
    // row sums: reduce over tc; only fh==0 writes (halves hold equal l)
    l0 += __shfl_xor_sync(0xffffffffu, l0, 1);
    l0 += __shfl_xor_sync(0xffffffffu, l0, 2);
    l1 += __shfl_xor_sync(0xffffffffu, l1, 1);
    l1 += __shfl_xor_sync(0xffffffffu, l1, 2);
    if (fh == 0 && tc == 0) {
        g_lpart[js][gr0] = l0;
        g_lpart[js][gr1] = l1;
    }
}

// ---------------------------------------------------------------------------
// Kernel E: combine partials, divide, ELU.
// ---------------------------------------------------------------------------
__global__ __launch_bounds__(256) void fixup_kernel(float* __restrict__ out) {
    const int idx = blockIdx.x * 256 + threadIdx.x;
    const int i = idx >> 4;
    const int f4 = (idx & 15) * 4;
    float4 acc = make_float4(0.f, 0.f, 0.f, 0.f);
    float l = 0.f;
#pragma unroll
    for (int js = 0; js < NSPLIT; js++) {
        const float4 dv = *(const float4*)&g_Dpart[js][(size_t)i * FOUT + f4];
        acc.x += dv.x; acc.y += dv.y; acc.z += dv.z; acc.w += dv.w;
        l += g_lpart[js][i];
    }
    const float inv = 1.f / l;
    float o0 = acc.x * inv, o1 = acc.y * inv, o2 = acc.z * inv, o3 = acc.w * inv;
    o0 = o0 > 0.f ? o0 : expm1f(o0);
    o1 = o1 > 0.f ? o1 : expm1f(o1);
    o2 = o2 > 0.f ? o2 : expm1f(o2);
    o3 = o3 > 0.f ? o3 : expm1f(o3);
    *(float4*)&out[(size_t)i * FOUT + f4] = make_float4(o0, o1, o2, o3);
}

// ---------------------------------------------------------------------------
extern "C" void kernel_launch(void* const* d_in, const int* in_sizes, int n_in,
                              void* d_out, int out_size) {
    const float* h = (const float*)d_in[0];
    const int* adj = (const int*)d_in[1];
    const float* W = (const float*)d_in[2];
    const float* a = (const float*)d_in[3];
    float* out = (float*)d_out;

    wh_mask_kernel<<<512 + 4096, 256>>>(h, W, adj);
    fvec_kernel<<<N / 256, 256>>>(a);
    bfrag_kernel<<<512, 256>>>();
    gat_mma_kernel<<<(N / NTILE) * NSPLIT, 512>>>();
    fixup_kernel<<<N * 16 / 256, 256>>>(out);
}

// round 14
// speedup vs baseline: 1.3147x; 1.3147x over previous
#include <cuda_runtime.h>
#include <cuda_bf16.h>
#include <math.h>
#include <stdint.h>

#define N 8192
#define FIN 256
#define FOUT 64
#define NSPLIT 8    // j-splits per i-tile
#define NTILE 128   // i-rows per CTA
#define JSTEP 32    // j per pipeline step
#define NST 32      // steps per CTA (1024 j per split)
#define PIPE 4      // per-warp ring depth
#define WSTR 36     // padded row stride (ints) -> conflict-free LDS
#define WBUF (16 * WSTR)

// ---------------- device scratch ----------------
__device__ float    g_Wh[(size_t)N * FOUT];
__device__ uint4    g_Bfrag[512 * 2 * 4 * 32];  // tf32 B fragments, 2 MB
__device__ float    g_E1[N];
__device__ float    g_E2[N];
__device__ float    g_fsrc[N];
__device__ unsigned g_gmax_enc;
__device__ float    g_Dpart[NSPLIT][(size_t)N * FOUT];
__device__ float    g_lpart[NSPLIT][N];

// ---------------- helpers ----------------
#define CP_ASYNC16(saddr, gptr) \
    asm volatile("cp.async.cg.shared.global [%0], [%1], 16;" ::"r"(saddr), "l"(gptr))
#define CP_COMMIT() asm volatile("cp.async.commit_group;")
#define CP_WAIT(n)  asm volatile("cp.async.wait_group %0;" ::"n"(n))
#define MUL_F32X2(d, a, b) \
    asm("mul.rn.f32x2 %0, %1, %2;" : "=l"(d) : "l"(a), "l"(b))

__device__ __forceinline__ uint32_t f2tf32(float x) {
    uint32_t r;
    asm("cvt.rna.tf32.f32 %0, %1;" : "=r"(r) : "f"(x));
    return r;
}
__device__ __forceinline__ void mma_tf32(float* d, uint32_t a0, uint32_t a1,
                                         uint32_t a2, uint32_t a3, uint32_t b0,
                                         uint32_t b1) {
    asm volatile(
        "mma.sync.aligned.m16n8k8.row.col.f32.tf32.tf32.f32 "
        "{%0,%1,%2,%3}, {%4,%5,%6,%7}, {%8,%9}, {%0,%1,%2,%3};"
        : "+f"(d[0]), "+f"(d[1]), "+f"(d[2]), "+f"(d[3])
        : "r"(a0), "r"(a1), "r"(a2), "r"(a3), "r"(b0), "r"(b1));
}
__device__ __forceinline__ unsigned enc_f(float x) {
    unsigned b = __float_as_uint(x);
    return (b & 0x80000000u) ? ~b : (b | 0x80000000u);
}
__device__ __forceinline__ float dec_f(unsigned k) {
    return __uint_as_float((k & 0x80000000u) ? (k & 0x7fffffffu) : ~k);
}

// ---------------------------------------------------------------------------
// Kernel A: Wh = h @ W. k-outer/r-inner (Ws reuse across 4 rows).
// ---------------------------------------------------------------------------
__global__ __launch_bounds__(256, 4) void wh_kernel(const float* __restrict__ h,
                                                    const float* __restrict__ W) {
    __shared__ float Ws[128][FOUT];
    if (blockIdx.x == 0 && threadIdx.x == 0) g_gmax_enc = 0u;
    const int f = threadIdx.x & 63;
    const int g = threadIdx.x >> 6;
    const int row0 = blockIdx.x * 16 + g * 4;
    float acc0 = 0.f, acc1 = 0.f, acc2 = 0.f, acc3 = 0.f;
    for (int t = 0; t < 2; t++) {
        __syncthreads();
        for (int idx = threadIdx.x; idx < 128 * FOUT; idx += 256)
            (&Ws[0][0])[idx] = W[t * 128 * FOUT + idx];
        __syncthreads();
        const float4* h0 = (const float4*)(h + (size_t)(row0 + 0) * FIN + t * 128);
        const float4* h1 = (const float4*)(h + (size_t)(row0 + 1) * FIN + t * 128);
        const float4* h2 = (const float4*)(h + (size_t)(row0 + 2) * FIN + t * 128);
        const float4* h3 = (const float4*)(h + (size_t)(row0 + 3) * FIN + t * 128);
#pragma unroll 8
        for (int k4 = 0; k4 < 32; k4++) {
            const float4 v0 = h0[k4], v1 = h1[k4], v2 = h2[k4], v3 = h3[k4];
            const float w0 = Ws[k4 * 4 + 0][f];
            const float w1 = Ws[k4 * 4 + 1][f];
            const float w2 = Ws[k4 * 4 + 2][f];
            const float w3 = Ws[k4 * 4 + 3][f];
            acc0 += v0.x * w0 + v0.y * w1 + v0.z * w2 + v0.w * w3;
            acc1 += v1.x * w0 + v1.y * w1 + v1.z * w2 + v1.w * w3;
            acc2 += v2.x * w0 + v2.y * w1 + v2.z * w2 + v2.w * w3;
            acc3 += v3.x * w0 + v3.y * w1 + v3.z * w2 + v3.w * w3;
        }
    }
    g_Wh[(size_t)(row0 + 0) * FOUT + f] = acc0;
    g_Wh[(size_t)(row0 + 1) * FOUT + f] = acc1;
    g_Wh[(size_t)(row0 + 2) * FOUT + f] = acc2;
    g_Wh[(size_t)(row0 + 3) * FOUT + f] = acc3;
}

// ---------------------------------------------------------------------------
// Kernel B: f_src, E1=exp(f_dst), E2=exp(0.2 f_dst), fused global max(f_dst).
// ---------------------------------------------------------------------------
__global__ __launch_bounds__(256) void fvec_kernel(const float* __restrict__ a) {
    __shared__ unsigned smax[8];
    const int i = blockIdx.x * blockDim.x + threadIdx.x;
    const float4* w4 = (const float4*)(g_Wh + (size_t)i * FOUT);
    const float4* a4 = (const float4*)a;
    float s = 0.f, d = 0.f;
#pragma unroll
    for (int q = 0; q < 16; q++) {
        float4 v = w4[q], as_ = a4[q], ad = a4[16 + q];
        s += v.x * as_.x + v.y * as_.y + v.z * as_.z + v.w * as_.w;
        d += v.x * ad.x + v.y * ad.y + v.z * ad.z + v.w * ad.w;
    }
    g_fsrc[i] = s;
    g_E1[i] = __expf(d);
    g_E2[i] = __expf(0.2f * d);
    unsigned k = enc_f(d);
#pragma unroll
    for (int off = 16; off > 0; off >>= 1)
        k = max(k, __shfl_xor_sync(0xffffffffu, k, off));
    if ((threadIdx.x & 31) == 0) smax[threadIdx.x >> 5] = k;
    __syncthreads();
    if (threadIdx.x == 0) {
        unsigned m = smax[0];
#pragma unroll
        for (int w = 1; w < 8; w++) m = max(m, smax[w]);
        atomicMax(&g_gmax_enc, m);
    }
}

// ---------------------------------------------------------------------------
// Kernel B2: build tf32 B fragments of Wh for mma.m16n8k8.
// ---------------------------------------------------------------------------
__global__ __launch_bounds__(256) void bfrag_kernel() {
    const int wid = blockIdx.x * 8 + (threadIdx.x >> 5);  // 0..4095
    const int lane = threadIdx.x & 31;
    const int jblock = wid >> 3, kh = (wid >> 2) & 1, ntp = wid & 3;
    const int j0 = jblock * 16 + kh * 8;
    const int f0 = ntp * 16;
    const int g = lane >> 2, tc = lane & 3;
    uint4 b;
    b.x = f2tf32(g_Wh[(size_t)(j0 + tc) * FOUT + f0 + g]);
    b.y = f2tf32(g_Wh[(size_t)(j0 + tc + 4) * FOUT + f0 + g]);
    b.z = f2tf32(g_Wh[(size_t)(j0 + tc) * FOUT + f0 + 8 + g]);
    b.w = f2tf32(g_Wh[(size_t)(j0 + tc + 4) * FOUT + f0 + 8 + g]);
    g_Bfrag[(size_t)wid * 32 + lane] = b;
}

// ---------------------------------------------------------------------------
// Kernel C (main): D[128,64] += P[128,1024] @ Wh[1024,64] via mma.tf32.
// R9 structure (best measured): PER-WARP adj cp.async rings (PIPE=4), no CTA
// barriers in the loop, B fragments direct from L2.
// New: packed-f32x2 p-gen ({A1,A2}x{E1,E2} in one mul) and hoisted linear
// B-fragment addressing.
// ---------------------------------------------------------------------------
#define SADJW(w, b, r, c) \
    s_adj[(w) * (PIPE * WBUF) + (b) * WBUF + (r) * WSTR + (c)]

__global__ __launch_bounds__(256, 2) void gat_mma_kernel(const int* __restrict__ adj) {
    __shared__ int    s_adj[8 * PIPE * WBUF];  // 72 KB
    __shared__ float2 s_E[1024];               // 8 KB
    __shared__ float  sA1[NTILE], sA2[NTILE];

    const int tid = threadIdx.x, lane = tid & 31, warp = tid >> 5;
    const int g = lane >> 2, tc = lane & 3;
    const int it = blockIdx.x >> 3, js = blockIdx.x & 7;
    const int row0 = it * NTILE, jbase = js * (NST * JSTEP);

    // per-warp staging geometry: lane covers row strow (0..15), 16 ints
    // starting at stcol, as 4 x 16B segments.
    const int strow = lane >> 1, stcol = (lane & 1) * 16;
    const int* gsrc = adj + (size_t)(row0 + warp * 16 + strow) * N + jbase + stcol;
    const uint32_t sw_lane =
        (uint32_t)__cvta_generic_to_shared(&SADJW(warp, 0, strow, stcol));

    // prologue: stage tiles 0..PIPE-2
#pragma unroll
    for (int t = 0; t < PIPE - 1; t++) {
        const uint32_t sd = sw_lane + (uint32_t)(t * WBUF) * 4u;
#pragma unroll
        for (int q = 0; q < 4; q++)
            CP_ASYNC16(sd + q * 16, gsrc + t * JSTEP + q * 4);
        CP_COMMIT();
    }

    // stage E and per-row A1/A2 (CTA-wide, once)
    for (int k = tid; k < 1024; k += 256)
        s_E[k] = make_float2(g_E1[jbase + k], g_E2[jbase + k]);
    if (tid < NTILE) {
        const float fs = g_fsrc[row0 + tid];
        float M = fs + dec_f(g_gmax_enc);
        M = M > 0.f ? M : 0.2f * M;  // lrelu monotone -> valid row upper bound
        sA1[tid] = __expf(fs - M);
        sA2[tid] = __expf(0.2f * fs - M);
    }
    __syncthreads();

    const int lr0 = warp * 16 + g, lr1 = lr0 + 8;
    const int gr0 = row0 + lr0, gr1 = row0 + lr1;
    float2 A0f = make_float2(sA1[lr0], sA2[lr0]);
    float2 A1f = make_float2(sA1[lr1], sA2[lr1]);
    const unsigned long long Ap0 = *(unsigned long long*)&A0f;
    const unsigned long long Ap1 = *(unsigned long long*)&A1f;

    float d[8][4];
#pragma unroll
    for (int nt = 0; nt < 8; nt++)
#pragma unroll
        for (int q = 0; q < 4; q++) d[nt][q] = 0.f;
    float l0 = 0.f, l1 = 0.f;

    for (int s = 0; s < NST; s++) {
        const int buf = s % PIPE;
        CP_WAIT(PIPE - 2);  // tile s arrived (later groups may be in flight)
        __syncwarp();

        // stage tile s+PIPE-1 into ring slot (s-1)%PIPE (consumed last iter);
        // ALWAYS commit a group so wait counts stay exact.
        if (s + PIPE - 1 < NST) {
            const int t = s + PIPE - 1;
            const uint32_t sd = sw_lane + (uint32_t)((t % PIPE) * WBUF) * 4u;
#pragma unroll
            for (int q = 0; q < 4; q++)
                CP_ASYNC16(sd + q * 16, gsrc + t * JSTEP + q * 4);
        }
        CP_COMMIT();

        // ---- p for 2 rows x 8 cols {tc + 4cq}: packed f32x2 mul + FMNMX ----
        const int jl = s * JSTEP;
        float p0[8], p1[8];
#pragma unroll
        for (int cq = 0; cq < 8; cq++) {
            const int c = tc + cq * 4;
            const unsigned long long e =
                *(const unsigned long long*)&s_E[jl + c];
            unsigned long long t0, t1;
            MUL_F32X2(t0, Ap0, e);  // {A1*E1, A2*E2}
            MUL_F32X2(t1, Ap1, e);
            float v0 = fmaxf(__uint_as_float((unsigned)t0),
                             __uint_as_float((unsigned)(t0 >> 32)));
            float v1 = fmaxf(__uint_as_float((unsigned)t1),
                             __uint_as_float((unsigned)(t1 >> 32)));
            p0[cq] = SADJW(warp, buf, g, c) ? v0 : 0.f;
            p1[cq] = SADJW(warp, buf, g + 8, c) ? v1 : 0.f;
            l0 += p0[cq];
            l1 += p1[cq];
        }

        // ---- 4 K-groups of 8 j: MMAs (B fragments from L2) ----
        // fragment unit index = (js*64 + 2s)*2 + kk; unit = 4 groups of 32.
        const uint4* fp =
            &g_Bfrag[(size_t)((js * 64 + 2 * s) * 2) * 4 * 32 + lane];
#pragma unroll
        for (int kk = 0; kk < 4; kk++) {
            const uint4* bp = fp + (size_t)kk * 128;
            const uint32_t a0 = f2tf32(p0[kk * 2]);
            const uint32_t a1 = f2tf32(p1[kk * 2]);
            const uint32_t a2 = f2tf32(p0[kk * 2 + 1]);
            const uint32_t a3 = f2tf32(p1[kk * 2 + 1]);
            const uint4 B0 = bp[0];
            const uint4 B1 = bp[32];
            const uint4 B2 = bp[64];
            const uint4 B3 = bp[96];
            mma_tf32(d[0], a0, a1, a2, a3, B0.x, B0.y);
            mma_tf32(d[1], a0, a1, a2, a3, B0.z, B0.w);
            mma_tf32(d[2], a0, a1, a2, a3, B1.x, B1.y);
            mma_tf32(d[3], a0, a1, a2, a3, B1.z, B1.w);
            mma_tf32(d[4], a0, a1, a2, a3, B2.x, B2.y);
            mma_tf32(d[5], a0, a1, a2, a3, B2.z, B2.w);
            mma_tf32(d[6], a0, a1, a2, a3, B3.x, B3.y);
            mma_tf32(d[7], a0, a1, a2, a3, B3.z, B3.w);
        }
    }

    // write D partials
#pragma unroll
    for (int nt = 0; nt < 8; nt++) {
        const int f = nt * 8 + 2 * tc;
        *(float2*)&g_Dpart[js][(size_t)gr0 * FOUT + f] =
            make_float2(d[nt][0], d[nt][1]);
        *(float2*)&g_Dpart[js][(size_t)gr1 * FOUT + f] =
            make_float2(d[nt][2], d[nt][3]);
    }
    // row sums: reduce over tc (lanes g*4..g*4+3)
    l0 += __shfl_xor_sync(0xffffffffu, l0, 1);
    l0 += __shfl_xor_sync(0xffffffffu, l0, 2);
    l1 += __shfl_xor_sync(0xffffffffu, l1, 1);
    l1 += __shfl_xor_sync(0xffffffffu, l1, 2);
    if (tc == 0) {
        g_lpart[js][gr0] = l0;
        g_lpart[js][gr1] = l1;
    }
}

// ---------------------------------------------------------------------------
// Kernel E: combine partials, divide, ELU.
// ---------------------------------------------------------------------------
__global__ __launch_bounds__(256) void fixup_kernel(float* __restrict__ out) {
    const int idx = blockIdx.x * 256 + threadIdx.x;
    const int i = idx >> 4;
    const int f4 = (idx & 15) * 4;
    float4 acc = make_float4(0.f, 0.f, 0.f, 0.f);
    float l = 0.f;
#pragma unroll
    for (int js = 0; js < NSPLIT; js++) {
        const float4 dv = *(const float4*)&g_Dpart[js][(size_t)i * FOUT + f4];
        acc.x += dv.x; acc.y += dv.y; acc.z += dv.z; acc.w += dv.w;
        l += g_lpart[js][i];
    }
    const float inv = 1.f / l;
    float o0 = acc.x * inv, o1 = acc.y * inv, o2 = acc.z * inv, o3 = acc.w * inv;
    o0 = o0 > 0.f ? o0 : expm1f(o0);
    o1 = o1 > 0.f ? o1 : expm1f(o1);
    o2 = o2 > 0.f ? o2 : expm1f(o2);
    o3 = o3 > 0.f ? o3 : expm1f(o3);
    *(float4*)&out[(size_t)i * FOUT + f4] = make_float4(o0, o1, o2, o3);
}

// ---------------------------------------------------------------------------
extern "C" void kernel_launch(void* const* d_in, const int* in_sizes, int n_in,
                              void* d_out, int out_size) {
    const float* h = (const float*)d_in[0];
    const int* adj = (const int*)d_in[1];
    const float* W = (const float*)d_in[2];
    const float* a = (const float*)d_in[3];
    float* out = (float*)d_out;

    wh_kernel<<<N / 16, 256>>>(h, W);
    fvec_kernel<<<N / 256, 256>>>(a);
    bfrag_kernel<<<512, 256>>>();
    gat_mma_kernel<<<(N / NTILE) * NSPLIT, 256>>>(adj);
    fixup_kernel<<<N * 16 / 256, 256>>>(out);
}